// round 14
// baseline (speedup 1.0000x reference)
#include <cuda_runtime.h>
#include <cuda_fp16.h>
#include <math.h>

#define NN 50000
#define MM 50000
#define EE 1600000
#define DD 128
#define SW 136   // smem tile stride in halves (272B: ldmatrix-aligned, conflict-free)

// Scratch (allocation-free rule: __device__ globals)
__device__ __half g_qh[NN * DD];
__device__ __half g_k[MM * DD];
__device__ __half g_v[MM * DD];
__device__ float  g_p[EE];        // exp(score) per edge
__device__ int    g_rowptr[NN + 1];

__device__ __forceinline__ float gelu_fast(float x) {
    float u = x * fmaf(x * x, 0.0356774081f, 0.7978845608f);
    float th;
    asm("tanh.approx.f32 %0, %1;" : "=f"(th) : "f"(u));
    return 0.5f * x * (1.0f + th);
}

__device__ __forceinline__ void mma16816(float* c,
    unsigned a0, unsigned a1, unsigned a2, unsigned a3,
    unsigned b0, unsigned b1)
{
    asm volatile(
        "mma.sync.aligned.m16n8k16.row.col.f32.f16.f16.f32 "
        "{%0,%1,%2,%3}, {%4,%5,%6,%7}, {%8,%9}, {%0,%1,%2,%3};\n"
        : "+f"(c[0]), "+f"(c[1]), "+f"(c[2]), "+f"(c[3])
        : "r"(a0), "r"(a1), "r"(a2), "r"(a3), "r"(b0), "r"(b1));
}

// ---------------------------------------------------------------------------
// Tensor-core projection: Y = gelu(X @ W + b), fp16 HMMA, fp32 accum.
// (unchanged — measured stable; ldmatrix A/B, coalesced epilogue)
// ---------------------------------------------------------------------------
__global__ __launch_bounds__(256, 2) void proj_mma_kernel(
    const float* __restrict__ query, const float* __restrict__ memory,
    const float* __restrict__ Wq, const float* __restrict__ bq,
    const float* __restrict__ Wk, const float* __restrict__ bk,
    const float* __restrict__ Wv, const float* __restrict__ bv)
{
    extern __shared__ __half smem[];
    __half* sW = smem;             // 128 x SW halves
    __half* sX = smem + 128 * SW;  // 128 x SW halves (reused for output)

    const float* X; const float* W; const float* b; __half* Y;
    if (blockIdx.y == 0)      { X = query;  W = Wq; b = bq; Y = g_qh; }
    else if (blockIdx.y == 1) { X = memory; W = Wk; b = bk; Y = g_k; }
    else                      { X = memory; W = Wv; b = bv; Y = g_v; }
    const int R = NN;

    const int t = threadIdx.x;
    const int row_base = blockIdx.x * 128;

    {
        const float2* W2 = (const float2*)W;
        const float2* X2 = (const float2*)X;
        #pragma unroll
        for (int i = t; i < 8192; i += 256) {
            int row = i >> 6;
            int col = (i & 63) * 2;
            float2 wv = W2[i];
            *(__half2*)(sW + row * SW + col) = __floats2half2_rn(wv.x, wv.y);
            int xr = row_base + row;
            if (xr > R - 1) xr = R - 1;
            float2 xv = X2[(size_t)xr * 64 + (i & 63)];
            *(__half2*)(sX + row * SW + col) = __floats2half2_rn(xv.x, xv.y);
        }
    }
    __syncthreads();

    const int w = t >> 5;
    const int lane = t & 31;
    const int g = lane >> 2;
    const int tg = lane & 3;
    const int mloc = w * 16;

    float acc[16][4];
    #pragma unroll
    for (int i = 0; i < 16; i++) {
        acc[i][0] = 0.f; acc[i][1] = 0.f; acc[i][2] = 0.f; acc[i][3] = 0.f;
    }

    const int a_row = mloc + (lane & 15);
    const int a_koff = (lane >> 4) << 3;
    const int lrow = lane & 15;
    const int lcoff = (lane >> 4) << 3;

    #pragma unroll
    for (int ks = 0; ks < 8; ks++) {
        unsigned a0, a1, a2, a3;
        unsigned abase = (unsigned)__cvta_generic_to_shared(
            sX + a_row * SW + ks * 16 + a_koff);
        asm volatile(
            "ldmatrix.sync.aligned.m8n8.x4.shared.b16 {%0,%1,%2,%3}, [%4];\n"
            : "=r"(a0), "=r"(a1), "=r"(a2), "=r"(a3) : "r"(abase));

        unsigned bbase = (unsigned)__cvta_generic_to_shared(
            sW + (ks * 16 + lrow) * SW + lcoff);
        #pragma unroll
        for (int nt = 0; nt < 16; nt += 2) {
            unsigned b0, b1, b2, b3;
            asm volatile(
                "ldmatrix.sync.aligned.m8n8.x4.trans.shared.b16 "
                "{%0,%1,%2,%3}, [%4];\n"
                : "=r"(b0), "=r"(b1), "=r"(b2), "=r"(b3)
                : "r"(bbase + (unsigned)(nt * 8 * 2)));
            mma16816(acc[nt],     a0, a1, a2, a3, b0, b1);
            mma16816(acc[nt + 1], a0, a1, a2, a3, b2, b3);
        }
    }

    __syncthreads();
    #pragma unroll
    for (int nt = 0; nt < 16; nt++) {
        int col = nt * 8 + 2 * tg;
        float2 bias = *(const float2*)(b + col);
        float o0 = gelu_fast(acc[nt][0] + bias.x);
        float o1 = gelu_fast(acc[nt][1] + bias.y);
        float o2 = gelu_fast(acc[nt][2] + bias.x);
        float o3 = gelu_fast(acc[nt][3] + bias.y);
        *(__half2*)(sX + (mloc + g) * SW + col)     = __floats2half2_rn(o0, o1);
        *(__half2*)(sX + (mloc + 8 + g) * SW + col) = __floats2half2_rn(o2, o3);
    }
    __syncthreads();

    {
        const int lr = t >> 4;
        const int c16 = t & 15;
        #pragma unroll
        for (int it = 0; it < 8; it++) {
            int row_local = it * 16 + lr;
            int row = row_base + row_local;
            if (row < R) {
                uint4 val = *(const uint4*)(sX + row_local * SW + c16 * 8);
                *(uint4*)(Y + (size_t)row * DD + c16 * 8) = val;
            }
        }
    }
}

// ---------------------------------------------------------------------------
// CSR row pointers from sorted rows[] via lower_bound.
// ---------------------------------------------------------------------------
__global__ void build_rowptr(const int* __restrict__ rows) {
    int i = blockIdx.x * blockDim.x + threadIdx.x;
    if (i > NN) return;
    int lo = 0, hi = EE;
    while (lo < hi) {
        int mid = (lo + hi) >> 1;
        if (rows[mid] < i) lo = mid + 1; else hi = mid;
    }
    g_rowptr[i] = lo;
}

// ---------------------------------------------------------------------------
// Edge-parallel: p_e = exp(q.k * adj * scale). 4 lanes/edge, HFMA2 dot.
// No max subtraction: gelu-bounded scores make plain exp safe, and
// exp(s)/sum(exp(s)) is identical to the shifted form.
// ---------------------------------------------------------------------------
__global__ __launch_bounds__(256) void score_kernel(
    const int* __restrict__ rows, const int* __restrict__ cols,
    const float* __restrict__ adj)
{
    int idx = blockIdx.x * 256 + threadIdx.x;
    int e = idx >> 2;
    if (e >= EE) return;
    int sub = idx & 3;

    int r = rows[e];
    int c = cols[e];
    const uint4* qp = (const uint4*)(g_qh + (size_t)r * DD + sub * 32);
    const uint4* kp = (const uint4*)(g_k  + (size_t)c * DD + sub * 32);

    __half2 z = __floats2half2_rn(0.f, 0.f);
    __half2 ac0 = z, ac1 = z, ac2 = z, ac3 = z;
    #pragma unroll
    for (int i = 0; i < 4; i++) {
        uint4 a = qp[i];
        uint4 b = kp[i];
        ac0 = __hfma2(*(__half2*)&a.x, *(__half2*)&b.x, ac0);
        ac1 = __hfma2(*(__half2*)&a.y, *(__half2*)&b.y, ac1);
        ac2 = __hfma2(*(__half2*)&a.z, *(__half2*)&b.z, ac2);
        ac3 = __hfma2(*(__half2*)&a.w, *(__half2*)&b.w, ac3);
    }
    float2 f0 = __half22float2(ac0);
    float2 f1 = __half22float2(ac1);
    float2 f2 = __half22float2(ac2);
    float2 f3 = __half22float2(ac3);
    float s = ((f0.x + f0.y) + (f1.x + f1.y))
            + ((f2.x + f2.y) + (f3.x + f3.y));

    s += __shfl_xor_sync(0xFFFFFFFFu, s, 1);
    s += __shfl_xor_sync(0xFFFFFFFFu, s, 2);

    if (sub == 0) {
        float m = adj[e] * 0.1275611217f;   // (1/sqrt(128)) * log2(e)
        g_p[e] = exp2f(s * m);
    }
}

// ---------------------------------------------------------------------------
// Warp-per-row, 4 edges per iteration:
// quarter-warp q (8 lanes) handles edge e+q; each lane loads 2 uint4
// (16 dims) of that edge's v-row. ~9.5 warp-instr/edge, 2x iteration
// count reduction vs 2-edge version, 4 LDG.128/warp in flight (unroll 2).
// Cross-quarter merge: 2 shfl stages x 17 values, once per row.
// ---------------------------------------------------------------------------
__global__ __launch_bounds__(256) void attn_row_kernel(
    const int* __restrict__ cols, float* __restrict__ out)
{
    int row = (blockIdx.x * blockDim.x + threadIdx.x) >> 5;
    int lane = threadIdx.x & 31;
    if (row >= NN) return;

    int e0 = g_rowptr[row];
    int e1 = g_rowptr[row + 1];

    float* orow = out + (size_t)row * DD;
    const int quad = lane >> 3;       // 0..3: which edge of the group
    const int l8 = lane & 7;          // dim group: 16 dims starting at l8*16

    if (e0 == e1) {
        if (quad == 0) {
            float4 z = {0.f, 0.f, 0.f, 0.f};
            #pragma unroll
            for (int j = 0; j < 4; j++)
                ((float4*)orow)[l8 * 4 + j] = z;
        }
        return;
    }

    float d = 0.f;
    float a[16];
    #pragma unroll
    for (int i = 0; i < 16; i++) a[i] = 0.f;

    const int elast = e1 - 1;

    #pragma unroll 2
    for (int e = e0; e < e1; e += 4) {
        int idx = e + quad;
        bool valid = idx <= elast;
        if (idx > elast) idx = elast;          // clamped: always a valid index
        int   c = cols[idx];
        float p = valid ? g_p[idx] : 0.f;

        const uint4* vp = (const uint4*)(g_v + (size_t)c * DD + l8 * 16);
        uint4 va = vp[0];
        uint4 vb = vp[1];

        d += p;
        float2 t0 = __half22float2(*(__half2*)&va.x);
        float2 t1 = __half22float2(*(__half2*)&va.y);
        float2 t2 = __half22float2(*(__half2*)&va.z);
        float2 t3 = __half22float2(*(__half2*)&va.w);
        a[0] = fmaf(p, t0.x, a[0]);  a[1] = fmaf(p, t0.y, a[1]);
        a[2] = fmaf(p, t1.x, a[2]);  a[3] = fmaf(p, t1.y, a[3]);
        a[4] = fmaf(p, t2.x, a[4]);  a[5] = fmaf(p, t2.y, a[5]);
        a[6] = fmaf(p, t3.x, a[6]);  a[7] = fmaf(p, t3.y, a[7]);
        float2 u0 = __half22float2(*(__half2*)&vb.x);
        float2 u1 = __half22float2(*(__half2*)&vb.y);
        float2 u2 = __half22float2(*(__half2*)&vb.z);
        float2 u3 = __half22float2(*(__half2*)&vb.w);
        a[8]  = fmaf(p, u0.x, a[8]);   a[9]  = fmaf(p, u0.y, a[9]);
        a[10] = fmaf(p, u1.x, a[10]);  a[11] = fmaf(p, u1.y, a[11]);
        a[12] = fmaf(p, u2.x, a[12]);  a[13] = fmaf(p, u2.y, a[13]);
        a[14] = fmaf(p, u3.x, a[14]);  a[15] = fmaf(p, u3.y, a[15]);
    }

    // merge quarters: lanes with equal l8 hold the same dim group
    #pragma unroll
    for (int off = 8; off <= 16; off <<= 1) {
        d += __shfl_xor_sync(0xFFFFFFFFu, d, off);
        #pragma unroll
        for (int i = 0; i < 16; i++)
            a[i] += __shfl_xor_sync(0xFFFFFFFFu, a[i], off);
    }

    if (quad == 0) {
        float inv = 1.f / d;
        #pragma unroll
        for (int j = 0; j < 4; j++) {
            float4 o = {a[j*4] * inv, a[j*4+1] * inv,
                        a[j*4+2] * inv, a[j*4+3] * inv};
            ((float4*)orow)[l8 * 4 + j] = o;
        }
    }
}

extern "C" void kernel_launch(void* const* d_in, const int* in_sizes, int n_in,
                              void* d_out, int out_size) {
    const float* query  = (const float*)d_in[0];
    const float* memory = (const float*)d_in[1];
    const float* adj    = (const float*)d_in[2];
    const float* Wq     = (const float*)d_in[3];
    const float* bq     = (const float*)d_in[4];
    const float* Wk     = (const float*)d_in[5];
    const float* bk     = (const float*)d_in[6];
    const float* Wv     = (const float*)d_in[7];
    const float* bv     = (const float*)d_in[8];
    const int*   rows   = (const int*)d_in[9];
    const int*   cols   = (const int*)d_in[10];
    float* out = (float*)d_out;

    const int smem_bytes = 2 * 128 * SW * sizeof(__half);  // 69632
    cudaFuncSetAttribute(proj_mma_kernel,
                         cudaFuncAttributeMaxDynamicSharedMemorySize, smem_bytes);

    dim3 pgrid((NN + 127) / 128, 3);
    proj_mma_kernel<<<pgrid, 256, smem_bytes>>>(query, memory,
                                                Wq, bq, Wk, bk, Wv, bv);
    build_rowptr<<<(NN + 1 + 255) / 256, 256>>>(rows);
    score_kernel<<<(EE * 4 + 255) / 256, 256>>>(rows, cols, adj);
    attn_row_kernel<<<(NN * 32 + 255) / 256, 256>>>(cols, out);
}